// round 15
// baseline (speedup 1.0000x reference)
#include <cuda_runtime.h>
#include <cuda_fp16.h>
#include <cstdint>

#define DB 4096   // batch rows
#define DL 4096   // labels
#define DH 1024   // hidden

#define TILE_M 128
#define TILE_N 128
#define KCH 64
#define NCHUNK (DH / KCH)   // 16
#define STAGES 3

// per-stage smem: A(16K) B(16K) — rows of 64 fp16 = 128B, SW128 swizzle
#define ST_A 0
#define ST_B 16384
#define STAGE_BYTES 32768
#define SMEM_DYN (STAGES * STAGE_BYTES)   // 98304 -> 2 CTAs/SM

// ---------------- scratch (static device arrays: allowed) ----------------
__device__ __half g_x[(size_t)DB * DH];
__device__ __half g_w[(size_t)DL * DH];
__device__ float g_diag[DL];

// ---------------- helpers ----------------
__device__ __forceinline__ uint32_t smem_u32(const void* p) {
    uint32_t a;
    asm("{ .reg .u64 t; cvta.to.shared.u64 t, %1; cvt.u32.u64 %0, t; }" : "=r"(a) : "l"(p));
    return a;
}
__device__ __forceinline__ uint32_t swz(uint32_t b) {   // SW128: 16B chunk ^= row%8
    return b ^ ((b >> 3) & 0x70);
}
__device__ __forceinline__ void cp16(uint32_t dst, const void* gsrc) {
    asm volatile("cp.async.cg.shared.global [%0], [%1], 16;" :: "r"(dst), "l"(gsrc));
}
__device__ __forceinline__ void cp_commit() {
    asm volatile("cp.async.commit_group;");
}
__device__ __forceinline__ void cp_wait0() {
    asm volatile("cp.async.wait_group 0;");
}
__device__ __forceinline__ void ldm_x4(uint32_t addr, uint32_t* r) {
    asm volatile("ldmatrix.sync.aligned.m8n8.x4.shared.b16 {%0,%1,%2,%3}, [%4];"
                 : "=r"(r[0]), "=r"(r[1]), "=r"(r[2]), "=r"(r[3]) : "r"(addr));
}
__device__ __forceinline__ void mma4(float* c, const uint32_t* a, uint32_t b0, uint32_t b1) {
    asm volatile(
        "mma.sync.aligned.m16n8k16.row.col.f32.f16.f16.f32 "
        "{%0,%1,%2,%3},{%4,%5,%6,%7},{%8,%9},{%0,%1,%2,%3};"
        : "+f"(c[0]), "+f"(c[1]), "+f"(c[2]), "+f"(c[3])
        : "r"(a[0]), "r"(a[1]), "r"(a[2]), "r"(a[3]), "r"(b0), "r"(b1));
}

// ---------------- fused convert kernel ----------------
__global__ void __launch_bounds__(256) k_convert(const float* __restrict__ x,
                                                 const float* __restrict__ W,
                                                 const float* __restrict__ E,
                                                 const float* __restrict__ b) {
    const int t = threadIdx.x;
    if (blockIdx.x < DL) {
        const int j = blockIdx.x;                 // label row
        size_t i4 = (size_t)j * 256 + t;          // one float4 each (1024 cols)
        float4 w = reinterpret_cast<const float4*>(W)[i4];
        float4 e = reinterpret_cast<const float4*>(E)[i4];
        ushort4 h;
        h.x = __half_as_ushort(__float2half_rn(w.x));
        h.y = __half_as_ushort(__float2half_rn(w.y));
        h.z = __half_as_ushort(__float2half_rn(w.z));
        h.w = __half_as_ushort(__float2half_rn(w.w));
        reinterpret_cast<ushort4*>(g_w)[i4] = h;

        float acc = w.x * e.x + w.y * e.y + w.z * e.z + w.w * e.w;
        #pragma unroll
        for (int o = 16; o > 0; o >>= 1) acc += __shfl_xor_sync(0xFFFFFFFFu, acc, o);
        __shared__ float red[8];
        if ((t & 31) == 0) red[t >> 5] = acc;
        __syncthreads();
        if (t == 0) {
            float s = 0.f;
            #pragma unroll
            for (int k = 0; k < 8; k++) s += red[k];
            g_diag[j] = s + b[j];
        }
    } else {
        size_t i = (size_t)(blockIdx.x - DL) * 512 + t;   // two float4 each
        float4 v0 = reinterpret_cast<const float4*>(x)[i];
        float4 v1 = reinterpret_cast<const float4*>(x)[i + 256];
        ushort4 h0, h1;
        h0.x = __half_as_ushort(__float2half_rn(v0.x));
        h0.y = __half_as_ushort(__float2half_rn(v0.y));
        h0.z = __half_as_ushort(__float2half_rn(v0.z));
        h0.w = __half_as_ushort(__float2half_rn(v0.w));
        h1.x = __half_as_ushort(__float2half_rn(v1.x));
        h1.y = __half_as_ushort(__float2half_rn(v1.y));
        h1.z = __half_as_ushort(__float2half_rn(v1.z));
        h1.w = __half_as_ushort(__float2half_rn(v1.w));
        reinterpret_cast<ushort4*>(g_x)[i] = h0;
        reinterpret_cast<ushort4*>(g_x)[i + 256] = h1;
    }
}

// -- GEMM: 128x128 CTA, 64x32 warp tile, 3-stage, seamless frag pipeline ----
// cp.async issue is distributed one-per-u-step across the MMA loop.
__global__ void __launch_bounds__(256, 2) k_gemm(float* __restrict__ out) {
    extern __shared__ char smraw[];
    const uint32_t sb = smem_u32(smraw);
    const int tid = threadIdx.x;
    const int lane = tid & 31;
    const int wid = tid >> 5;
    const int warpM = wid & 1;   // 2 warps in M (64 rows each)
    const int warpN = wid >> 1;  // 4 warps in N (32 cols each)
    const int row0 = blockIdx.y * TILE_M;
    const int col0 = blockIdx.x * TILE_N;

    // cp.async addressing: j*32 rows keeps row%8, so swizzle is j-invariant
    const int rsub = tid >> 3;                 // 0..31
    const int c16 = tid & 7;                   // 16B chunk within 128B row
    const uint32_t swzbase = swz((uint32_t)(rsub * 128 + c16 * 16));
    const char* baseA = (const char*)g_x + ((size_t)(row0 + rsub) * DH + c16 * 8) * 2;
    const char* baseB = (const char*)g_w + ((size_t)(col0 + rsub) * DH + c16 * 8) * 2;

    auto issueAll = [&](int chunk) {           // prologue bulk form
        const uint32_t sst = sb + (chunk % STAGES) * STAGE_BYTES;
        const char* pa = baseA + chunk * (KCH * 2);
        const char* pb = baseB + chunk * (KCH * 2);
        #pragma unroll
        for (int j = 0; j < 4; j++)
            cp16(sst + ST_A + swzbase + j * 4096, pa + (size_t)j * (32 * DH * 2));
        #pragma unroll
        for (int j = 0; j < 4; j++)
            cp16(sst + ST_B + swzbase + j * 4096, pb + (size_t)j * (32 * DH * 2));
    };

    float acc[4][4][4];
    #pragma unroll
    for (int mt = 0; mt < 4; mt++)
        #pragma unroll
        for (int nt = 0; nt < 4; nt++)
            #pragma unroll
            for (int q = 0; q < 4; q++) acc[mt][nt][q] = 0.f;

    issueAll(0); cp_commit();
    issueAll(1); cp_commit();

    const int lrow = lane & 15;
    const int lhalf = (lane >> 4) << 4;
    uint32_t lsw[4];
    #pragma unroll
    for (int ks = 0; ks < 4; ks++)
        lsw[ks] = swz((uint32_t)(lrow * 128 + ks * 32 + lhalf));

    uint32_t aa[4][4];      // A frag ring, prefetch distance 3 (16 % 4 == 0: phase-stable)
    uint32_t bb[2][2][4];   // B frags, ks-parity double buffer (4 ks: phase-stable)

    // prologue: slot 0 resident; preload frags for u = 0,1,2 and ks = 0
    cp_wait0();
    __syncthreads();
    {
        const uint32_t a0 = sb + ST_A + warpM * 8192;
        const uint32_t b0 = sb + ST_B + warpN * 4096;
        ldm_x4(a0 + lsw[0], aa[0]);
        ldm_x4(a0 + lsw[0] + 2048, aa[1]);
        ldm_x4(a0 + lsw[0] + 4096, aa[2]);
        ldm_x4(b0 + lsw[0], bb[0][0]);
        ldm_x4(b0 + lsw[0] + 2048, bb[0][1]);
    }

    #pragma unroll 1
    for (int c = 0; c < NCHUNK; c++) {
        cp_wait0();                      // slots c and c+1 both resident
        __syncthreads();                 // everyone done reading slot (c+2)%3
        const bool feed = (c + 2 < NCHUNK);
        const uint32_t sst2 = sb + ((c + 2) % STAGES) * STAGE_BYTES;
        const char* pa2 = baseA + (c + 2) * (KCH * 2);
        const char* pb2 = baseB + (c + 2) * (KCH * 2);

        const uint32_t s0 = sb + (c % STAGES) * STAGE_BYTES;
        const uint32_t s1 = sb + ((c + 1) % STAGES) * STAGE_BYTES;
        const uint32_t abase = s0 + ST_A + warpM * 8192;
        const uint32_t bbase = s0 + ST_B + warpN * 4096;
        const uint32_t abase_n = s1 + ST_A + warpM * 8192;
        const uint32_t bbase_n = s1 + ST_B + warpN * 4096;

        #pragma unroll
        for (int u = 0; u < 16; u++) {
            const int ks = u >> 2, mt = u & 3;
            // distributed cp.async: one 16B op per u-step for u = 0..7
            if (u < 4) {
                if (feed) cp16(sst2 + ST_A + swzbase + u * 4096,
                               pa2 + (size_t)u * (32 * DH * 2));
            } else if (u < 8) {
                if (feed) cp16(sst2 + ST_B + swzbase + (u - 4) * 4096,
                               pb2 + (size_t)(u - 4) * (32 * DH * 2));
            }
            {   // A prefetch, distance 3 (crosses into next chunk's slot at the seam)
                const int u3 = u + 3;
                if (u3 < 16) ldm_x4(abase + lsw[u3 >> 2] + (u3 & 3) * 2048, aa[u3 & 3]);
                else         ldm_x4(abase_n + lsw[0] + (u3 - 16) * 2048, aa[u3 & 3]);
            }
            if (mt == 0) {   // B prefetch for next ks (or next chunk's ks=0 at the seam)
                if (ks < 3) {
                    ldm_x4(bbase + lsw[ks + 1], bb[(ks + 1) & 1][0]);
                    ldm_x4(bbase + lsw[ks + 1] + 2048, bb[(ks + 1) & 1][1]);
                } else {
                    ldm_x4(bbase_n + lsw[0], bb[0][0]);
                    ldm_x4(bbase_n + lsw[0] + 2048, bb[0][1]);
                }
            }
            const uint32_t* a = aa[u & 3];
            #pragma unroll
            for (int nt = 0; nt < 4; nt++) {
                const int r = nt >> 1, p = nt & 1;
                mma4(acc[mt][nt], a, bb[ks & 1][r][p], bb[ks & 1][r][p + 2]);
            }
        }
        cp_commit();                     // commit this chunk's distributed loads
    }

    // ---- epilogue: add diag bias, store float2 pairs ----
    const int gid = lane >> 2;
    const int qid = lane & 3;
    const int mrow = row0 + warpM * 64 + gid;
    const int ncol = col0 + warpN * 32 + qid * 2;
    #pragma unroll
    for (int nt = 0; nt < 4; nt++) {
        const int n = ncol + nt * 8;
        const float2 d = *reinterpret_cast<const float2*>(&g_diag[n]);
        #pragma unroll
        for (int mt = 0; mt < 4; mt++) {
            const int m = mrow + mt * 16;
            float2 v0, v1;
            v0.x = acc[mt][nt][0] + d.x;
            v0.y = acc[mt][nt][1] + d.y;
            v1.x = acc[mt][nt][2] + d.x;
            v1.y = acc[mt][nt][3] + d.y;
            *reinterpret_cast<float2*>(&out[(size_t)m * DL + n]) = v0;
            *reinterpret_cast<float2*>(&out[(size_t)(m + 8) * DL + n]) = v1;
        }
    }
}

// ---------------- host ----------------
extern "C" void kernel_launch(void* const* d_in, const int* in_sizes, int n_in,
                              void* d_out, int out_size) {
    (void)in_sizes; (void)n_in; (void)out_size;
    const float* x = (const float*)d_in[0];
    const float* E = (const float*)d_in[1];
    const float* W = (const float*)d_in[2];
    const float* b = (const float*)d_in[3];
    float* out = (float*)d_out;

    k_convert<<<DL + (DB * DH / 4) / 512, 256>>>(x, W, E, b);

    cudaFuncSetAttribute(k_gemm, cudaFuncAttributeMaxDynamicSharedMemorySize, SMEM_DYN);

    dim3 grid(DL / TILE_N, DB / TILE_M);   // (32, 32)
    k_gemm<<<grid, 256, SMEM_DYN>>>(out);
}